// round 1
// baseline (speedup 1.0000x reference)
#include <cuda_runtime.h>
#include <math.h>

// ---------------------------------------------------------------------------
// WindowAttention (Swin): B_=256, N=98, DIM=768, NH=24, HD=32, NW=64
// Phase 1: QKV GEMM  (25088 x 768) @ (768 x 2304)^T + bias -> scatter Q/K/V
// Phase 2: per-(b,h) window attention with rel-pos bias + window mask
// ---------------------------------------------------------------------------

#define B_    256
#define NTOK  98
#define DIMC  768
#define NHEAD 24
#define HD    32
#define NWIN  64
#define SCALE 0.17677669529663687f   // 32^-0.5

#define GM (B_ * NTOK)     // 25088
#define GK DIMC            // 768
#define GN (3 * DIMC)      // 2304

// Scratch for Q/K/V in (b, h, n, d) layout. ~73.5 MB each.
__device__ float g_q[B_ * NHEAD * NTOK * HD];
__device__ float g_k[B_ * NHEAD * NTOK * HD];
__device__ float g_v[B_ * NHEAD * NTOK * HD];

// ------------------------- QKV GEMM ---------------------------------------
// C[m][c] = sum_k x[m][k] * w[c][k] + bias[c], scattered to g_q/g_k/g_v.
// Tile: BM=128, BN=64, BK=16, 256 threads, 8x4 microtile per thread.

#define BM 128
#define BN 64
#define BK 16
#define ASTRIDE 132   // padded (mult of 4 for float4 LDS alignment)
#define BSTRIDE 68

__global__ __launch_bounds__(256) void qkv_gemm(
    const float* __restrict__ x,
    const float* __restrict__ w,
    const float* __restrict__ bias)
{
    __shared__ __align__(16) float As_[BK * ASTRIDE];
    __shared__ __align__(16) float Bs_[BK * BSTRIDE];

    const int m0 = blockIdx.y * BM;
    const int c0 = blockIdx.x * BN;
    const int t  = threadIdx.x;
    const int tx = t & 15;        // 0..15  -> 4 output cols
    const int ty = t >> 4;        // 0..15  -> 8 output rows

    float acc[8][4];
#pragma unroll
    for (int i = 0; i < 8; i++)
#pragma unroll
        for (int j = 0; j < 4; j++) acc[i][j] = 0.0f;

    for (int k0 = 0; k0 < GK; k0 += BK) {
        // Load A tile (128x16) as 512 float4s, 2 per thread. Store transposed.
#pragma unroll
        for (int l = 0; l < 2; l++) {
            int p   = t + l * 256;
            int row = p >> 2;        // 0..127
            int kq  = p & 3;         // 0..3 (float4 group within k)
            float4 v = *(const float4*)(x + (size_t)(m0 + row) * GK + k0 + kq * 4);
            As_[(kq * 4 + 0) * ASTRIDE + row] = v.x;
            As_[(kq * 4 + 1) * ASTRIDE + row] = v.y;
            As_[(kq * 4 + 2) * ASTRIDE + row] = v.z;
            As_[(kq * 4 + 3) * ASTRIDE + row] = v.w;
        }
        // Load W tile (64x16) as 256 float4s, 1 per thread. Store transposed.
        {
            int row = t >> 2;        // 0..63
            int kq  = t & 3;
            float4 v = *(const float4*)(w + (size_t)(c0 + row) * GK + k0 + kq * 4);
            Bs_[(kq * 4 + 0) * BSTRIDE + row] = v.x;
            Bs_[(kq * 4 + 1) * BSTRIDE + row] = v.y;
            Bs_[(kq * 4 + 2) * BSTRIDE + row] = v.z;
            Bs_[(kq * 4 + 3) * BSTRIDE + row] = v.w;
        }
        __syncthreads();

#pragma unroll
        for (int k = 0; k < BK; k++) {
            float4 a0 = *(const float4*)&As_[k * ASTRIDE + ty * 8];
            float4 a1 = *(const float4*)&As_[k * ASTRIDE + ty * 8 + 4];
            float4 b0 = *(const float4*)&Bs_[k * BSTRIDE + tx * 4];
            float a[8] = {a0.x, a0.y, a0.z, a0.w, a1.x, a1.y, a1.z, a1.w};
            float b[4] = {b0.x, b0.y, b0.z, b0.w};
#pragma unroll
            for (int i = 0; i < 8; i++)
#pragma unroll
                for (int j = 0; j < 4; j++)
                    acc[i][j] += a[i] * b[j];
        }
        __syncthreads();
    }

    // Epilogue: add bias, scatter into (b, h, n, d) Q/K/V layouts.
    // c = h*96 + d*3 + s  (s: 0=q, 1=k, 2=v)
#pragma unroll
    for (int i = 0; i < 8; i++) {
        int m = m0 + ty * 8 + i;
        int b = m / NTOK;
        int n = m - b * NTOK;
#pragma unroll
        for (int j = 0; j < 4; j++) {
            int c = c0 + tx * 4 + j;
            float v = acc[i][j] + __ldg(&bias[c]);
            int s = c % 3;
            int d = (c / 3) & 31;
            int h = c / 96;
            size_t dst = ((((size_t)b * NHEAD + h) * NTOK + n) * HD) + d;
            if (s == 0)      g_q[dst] = v;
            else if (s == 1) g_k[dst] = v;
            else             g_v[dst] = v;
        }
    }
}

// ------------------------- Attention --------------------------------------
// One CTA per (h, b). 128 threads (4 warps). K/V staged in padded smem.
// Each warp owns query rows r = warp, warp+4, ...; lanes parallelize keys.

__global__ __launch_bounds__(128) void attn_kernel(
    const float* __restrict__ mask,
    const float* __restrict__ rel_table,
    const int*   __restrict__ rel_index,
    float* __restrict__ out)
{
    __shared__ float Ks[NTOK * 33];
    __shared__ float Vs[NTOK * 33];
    __shared__ float Ps[4][NTOK + 2];
    __shared__ float Qr[4][HD];

    const int h    = blockIdx.x;
    const int b    = blockIdx.y;
    const int t    = threadIdx.x;
    const int lane = t & 31;
    const int wrp  = t >> 5;

    const size_t base = (((size_t)b * NHEAD + h) * NTOK) * HD;

    // Stage K and V (coalesced reads, padded rows -> conflict-free LDS).
    for (int idx = t; idx < NTOK * HD; idx += 128) {
        int j = idx >> 5;
        int d = idx & 31;
        Ks[j * 33 + d] = g_k[base + idx];
        Vs[j * 33 + d] = g_v[base + idx];
    }
    __syncthreads();

    const float* maskw = mask + (size_t)(b & (NWIN - 1)) * NTOK * NTOK;

    for (int r = wrp; r < NTOK; r += 4) {
        // Load this row's q into registers via per-warp smem broadcast.
        Qr[wrp][lane] = g_q[base + r * HD + lane];
        __syncwarp();
        float qr[HD];
#pragma unroll
        for (int d = 0; d < HD; d++) qr[d] = Qr[wrp][d];

        // Scores: lane handles keys j = lane, lane+32, lane+64, lane+96.
        float s[4];
#pragma unroll
        for (int i = 0; i < 4; i++) {
            int j = lane + i * 32;
            if (j < NTOK) {
                float acc = 0.0f;
#pragma unroll
                for (int d = 0; d < HD; d++)
                    acc += qr[d] * Ks[j * 33 + d];
                int   ridx = __ldg(&rel_index[r * NTOK + j]);
                float bia  = __ldg(&rel_table[ridx * NHEAD + h]);
                s[i] = acc * SCALE + bia + __ldg(&maskw[r * NTOK + j]);
            } else {
                s[i] = -1e30f;
            }
        }

        // Softmax over the row (warp-wide reductions).
        float mx = fmaxf(fmaxf(s[0], s[1]), fmaxf(s[2], s[3]));
#pragma unroll
        for (int o = 16; o > 0; o >>= 1)
            mx = fmaxf(mx, __shfl_xor_sync(0xffffffffu, mx, o));

        float p[4];
        float sum = 0.0f;
#pragma unroll
        for (int i = 0; i < 4; i++) {
            p[i] = __expf(s[i] - mx);
            sum += p[i];
        }
#pragma unroll
        for (int o = 16; o > 0; o >>= 1)
            sum += __shfl_xor_sync(0xffffffffu, sum, o);
        float inv = 1.0f / sum;

#pragma unroll
        for (int i = 0; i < 4; i++) {
            int j = lane + i * 32;
            if (j < NTOK) Ps[wrp][j] = p[i] * inv;
        }
        __syncwarp();

        // out[d] = sum_j P[j] * V[j][d]; lane = d.
        float o = 0.0f;
        for (int j = 0; j < NTOK; j++)
            o += Ps[wrp][j] * Vs[j * 33 + lane];

        out[((size_t)b * NTOK + r) * DIMC + h * HD + lane] = o;
        __syncwarp();
    }
}

// ------------------------- launch ------------------------------------------

extern "C" void kernel_launch(void* const* d_in, const int* in_sizes, int n_in,
                              void* d_out, int out_size)
{
    const float* x         = (const float*)d_in[0];
    const float* mask      = (const float*)d_in[1];
    const float* qkv_w     = (const float*)d_in[2];
    const float* qkv_b     = (const float*)d_in[3];
    const float* rel_table = (const float*)d_in[4];
    const int*   rel_index = (const int*)  d_in[5];
    float* out = (float*)d_out;

    dim3 g1(GN / BN, GM / BM);      // (36, 196)
    qkv_gemm<<<g1, 256>>>(x, qkv_w, qkv_b);

    dim3 g2(NHEAD, B_);             // (24, 256)
    attn_kernel<<<g2, 128>>>(mask, rel_table, rel_index, out);
}

// round 3
// speedup vs baseline: 1.6063x; 1.6063x over previous
#include <cuda_runtime.h>
#include <cuda_bf16.h>
#include <math.h>
#include <stdint.h>

// ---------------------------------------------------------------------------
// WindowAttention (Swin): B_=256, N=98, DIM=768, NH=24, HD=32, NW=64
// Phase 1: QKV GEMM via mma.sync bf16 3-split (fp32 accuracy, legacy HMMA)
// Phase 2: per-(b,h) window attention (SIMT, smem)
// ---------------------------------------------------------------------------

#define B_    256
#define NTOK  98
#define DIMC  768
#define NHEAD 24
#define HD    32
#define NWIN  64
#define SCALE 0.17677669529663687f

#define GM (B_ * NTOK)     // 25088
#define GK DIMC            // 768
#define GN (3 * DIMC)      // 2304
#define KP (3 * GK)        // 2304  (split-K: A=[hi|lo|hi], B=[hi|hi|lo])

// Scratch
__device__ float g_q[B_ * NHEAD * NTOK * HD];
__device__ float g_k[B_ * NHEAD * NTOK * HD];
__device__ float g_v[B_ * NHEAD * NTOK * HD];
__device__ __nv_bfloat16 g_asplit[(size_t)GM * KP];
__device__ __nv_bfloat16 g_bsplit[(size_t)GN * KP];

// ---------------- helpers ---------------------------------------------------

__device__ __forceinline__ uint32_t smem_u32(const void* p) {
    uint32_t a;
    asm("{ .reg .u64 t; cvta.to.shared.u64 t, %1; cvt.u32.u64 %0, t; }" : "=r"(a) : "l"(p));
    return a;
}
#define CP16(dst, src) \
    asm volatile("cp.async.cg.shared.global [%0], [%1], 16;" :: "r"(dst), "l"(src) : "memory")
#define CP_COMMIT() asm volatile("cp.async.commit_group;" ::: "memory")
#define CP_WAIT(n)  asm volatile("cp.async.wait_group %0;" :: "n"(n) : "memory")

__device__ __forceinline__ void ldm_x4(uint32_t& r0, uint32_t& r1, uint32_t& r2,
                                       uint32_t& r3, uint32_t addr) {
    asm volatile("ldmatrix.sync.aligned.m8n8.x4.shared.b16 {%0,%1,%2,%3}, [%4];"
                 : "=r"(r0), "=r"(r1), "=r"(r2), "=r"(r3) : "r"(addr));
}
__device__ __forceinline__ void mma_bf16(float* c, const uint32_t* a, const uint32_t* b) {
    asm volatile(
        "mma.sync.aligned.m16n8k16.row.col.f32.bf16.bf16.f32 "
        "{%0,%1,%2,%3}, {%4,%5,%6,%7}, {%8,%9}, {%0,%1,%2,%3};"
        : "+f"(c[0]), "+f"(c[1]), "+f"(c[2]), "+f"(c[3])
        : "r"(a[0]), "r"(a[1]), "r"(a[2]), "r"(a[3]), "r"(b[0]), "r"(b[1]));
}

// ---------------- split-precision prep -------------------------------------

__global__ __launch_bounds__(256) void prep_a(const float* __restrict__ x) {
    int i = blockIdx.x * 256 + threadIdx.x;
    if (i >= GM * GK) return;
    int r = i / GK, k = i - r * GK;
    float f = x[i];
    __nv_bfloat16 hi = __float2bfloat16_rn(f);
    __nv_bfloat16 lo = __float2bfloat16_rn(f - __bfloat162float(hi));
    size_t base = (size_t)r * KP + k;
    g_asplit[base]          = hi;
    g_asplit[base + GK]     = lo;
    g_asplit[base + 2 * GK] = hi;
}

__global__ __launch_bounds__(256) void prep_b(const float* __restrict__ w) {
    int i = blockIdx.x * 256 + threadIdx.x;
    if (i >= GN * GK) return;
    int r = i / GK, k = i - r * GK;
    float f = w[i];
    __nv_bfloat16 hi = __float2bfloat16_rn(f);
    __nv_bfloat16 lo = __float2bfloat16_rn(f - __bfloat162float(hi));
    size_t base = (size_t)r * KP + k;
    g_bsplit[base]          = hi;
    g_bsplit[base + GK]     = hi;
    g_bsplit[base + 2 * GK] = lo;
}

// ---------------- QKV GEMM (mma.sync bf16) ----------------------------------
// BM=BN=128, BK=64. 256 thr = 8 warps (2m x 4n), warp tile 64x32.
// 3-stage cp.async pipeline; smem rows 128B, chunk^(row&7) XOR swizzle.

#define NSTAGE 3
#define CHUNKS (KP / 64)            // 36
#define STAGE_BYTES 32768           // A 16KB + B 16KB
#define SMEM_TOTAL (NSTAGE * STAGE_BYTES)   // 96KB

__global__ __launch_bounds__(256) void qkv_mma(const float* __restrict__ bias)
{
    extern __shared__ __align__(128) char smem[];
    const uint32_t sb = smem_u32(smem);

    const int tid  = threadIdx.x;
    const int lane = tid & 31;
    const int wid  = tid >> 5;
    const int wm   = wid & 1;       // warp m (0..1): 64 rows
    const int wn   = wid >> 1;      // warp n (0..3): 32 cols

    const int m0 = blockIdx.y * 128;
    const int c0 = blockIdx.x * 128;

    // --- cp.async source/dest precompute: 4 chunks each of A and B ----------
    // chunk id ci (0..1023): row = ci>>3, kchunk = ci&7
    const __nv_bfloat16* agbase = g_asplit + (size_t)m0 * KP;
    const __nv_bfloat16* bgbase = g_bsplit + (size_t)c0 * KP;

    int arow[4], akc[4];
#pragma unroll
    for (int l = 0; l < 4; l++) {
        int ci = tid + l * 256;
        arow[l] = ci >> 3;
        akc[l]  = ci & 7;
    }

    // --- ldmatrix lane addressing -------------------------------------------
    const int sub  = lane >> 3;           // 0..3
    const int lr   = (lane & 7) + ((sub & 1) << 3);   // row-within-16
    const int subh = sub >> 1;            // 16B half select

    // A: 4 m-tiles of 16 rows
    uint32_t a_rowoff[4];
    int      a_rx[4];
#pragma unroll
    for (int i = 0; i < 4; i++) {
        int row = wm * 64 + i * 16 + lr;
        a_rowoff[i] = (uint32_t)row * 128;
        a_rx[i]     = row & 7;
    }
    // B: 2 groups of 16 n-rows
    uint32_t b_rowoff[2];
    int      b_rx[2];
#pragma unroll
    for (int g = 0; g < 2; g++) {
        int row = wn * 32 + g * 16 + lr;
        b_rowoff[g] = (uint32_t)row * 128;
        b_rx[g]     = row & 7;
    }

    float acc[4][4][4];
#pragma unroll
    for (int i = 0; i < 4; i++)
#pragma unroll
        for (int j = 0; j < 4; j++)
#pragma unroll
            for (int q = 0; q < 4; q++) acc[i][j][q] = 0.0f;

    // --- prologue: issue stages 0,1 -----------------------------------------
#pragma unroll
    for (int c = 0; c < 2; c++) {
        uint32_t aB = sb + c * STAGE_BYTES;
        uint32_t bB = aB + 16384;
#pragma unroll
        for (int l = 0; l < 4; l++) {
            int r = arow[l], kc = akc[l];
            CP16(aB + r * 128 + ((kc ^ (r & 7)) << 4),
                 agbase + (size_t)r * KP + c * 64 + kc * 8);
            CP16(bB + r * 128 + ((kc ^ (r & 7)) << 4),
                 bgbase + (size_t)r * KP + c * 64 + kc * 8);
        }
        CP_COMMIT();
    }

    // --- main loop ----------------------------------------------------------
#pragma unroll 1
    for (int c = 0; c < CHUNKS; c++) {
        // issue chunk c+2 into stage (c+2)%3 (overwrites stage computed at c-1)
        if (c + 2 < CHUNKS) {
            int cs = c + 2;
            uint32_t aB = sb + (cs % NSTAGE) * STAGE_BYTES;
            uint32_t bB = aB + 16384;
#pragma unroll
            for (int l = 0; l < 4; l++) {
                int r = arow[l], kc = akc[l];
                CP16(aB + r * 128 + ((kc ^ (r & 7)) << 4),
                     agbase + (size_t)r * KP + cs * 64 + kc * 8);
                CP16(bB + r * 128 + ((kc ^ (r & 7)) << 4),
                     bgbase + (size_t)r * KP + cs * 64 + kc * 8);
            }
        }
        CP_COMMIT();
        CP_WAIT(2);
        __syncthreads();

        const uint32_t aB = sb + (c % NSTAGE) * STAGE_BYTES;
        const uint32_t bB = aB + 16384;

#pragma unroll
        for (int j = 0; j < 4; j++) {          // k16 index within chunk
            uint32_t af[4][4];
#pragma unroll
            for (int i = 0; i < 4; i++) {
                uint32_t addr = aB + a_rowoff[i]
                              + (uint32_t)(((j * 2 + subh) ^ a_rx[i]) << 4);
                ldm_x4(af[i][0], af[i][1], af[i][2], af[i][3], addr);
            }
            uint32_t bf[4][2];
#pragma unroll
            for (int g = 0; g < 2; g++) {
                uint32_t r0, r1, r2, r3;
                uint32_t addr = bB + b_rowoff[g]
                              + (uint32_t)(((j * 2 + subh) ^ b_rx[g]) << 4);
                ldm_x4(r0, r1, r2, r3, addr);
                bf[2 * g][0]     = r0; bf[2 * g][1]     = r2;
                bf[2 * g + 1][0] = r1; bf[2 * g + 1][1] = r3;
            }
#pragma unroll
            for (int i = 0; i < 4; i++)
#pragma unroll
                for (int n = 0; n < 4; n++)
                    mma_bf16(acc[i][n], af[i], bf[n]);
        }
        __syncthreads();
    }

    // --- epilogue: bias + scatter to g_q/g_k/g_v -----------------------------
    const int rbase = lane >> 2;      // 0..7
    const int cpair = lane & 3;
#pragma unroll
    for (int i = 0; i < 4; i++) {
#pragma unroll
        for (int half = 0; half < 2; half++) {
            int m = m0 + wm * 64 + i * 16 + rbase + half * 8;
            int b = m / NTOK;
            int tok = m - b * NTOK;
            size_t obase = (size_t)b * NHEAD * NTOK * HD + (size_t)tok * HD;
#pragma unroll
            for (int n = 0; n < 4; n++) {
#pragma unroll
                for (int e = 0; e < 2; e++) {
                    int cc = c0 + wn * 32 + n * 8 + cpair * 2 + e;
                    float v = acc[i][n][half * 2 + e] + __ldg(&bias[cc]);
                    int s3 = cc % 3;
                    int d  = (cc / 3) & 31;
                    int h  = cc / 96;
                    size_t dst = obase + (size_t)h * NTOK * HD + d;
                    if (s3 == 0)      g_q[dst] = v;
                    else if (s3 == 1) g_k[dst] = v;
                    else              g_v[dst] = v;
                }
            }
        }
    }
}

// ------------------------- Attention --------------------------------------

#define KSTR 36   // padded row stride (floats), float4-aligned, conflict-free

__global__ __launch_bounds__(128) void attn_kernel(
    const float* __restrict__ mask,
    const float* __restrict__ rel_table,
    const int*   __restrict__ rel_index,
    float* __restrict__ out)
{
    __shared__ __align__(16) float Ks[NTOK * KSTR];
    __shared__ __align__(16) float Vs[NTOK * KSTR];
    __shared__ float Ps[4][NTOK + 2];
    __shared__ __align__(16) float Qr[4][HD];

    const int h    = blockIdx.x;
    const int b    = blockIdx.y;
    const int t    = threadIdx.x;
    const int lane = t & 31;
    const int wrp  = t >> 5;

    const size_t base = (((size_t)b * NHEAD + h) * NTOK) * HD;

    for (int idx = t; idx < NTOK * HD; idx += 128) {
        int j = idx >> 5;
        int d = idx & 31;
        Ks[j * KSTR + d] = g_k[base + idx];
        Vs[j * KSTR + d] = g_v[base + idx];
    }
    __syncthreads();

    const float* maskw = mask + (size_t)(b & (NWIN - 1)) * NTOK * NTOK;

    for (int r = wrp; r < NTOK; r += 4) {
        Qr[wrp][lane] = g_q[base + r * HD + lane];
        __syncwarp();
        float4 q4[8];
#pragma unroll
        for (int dq = 0; dq < 8; dq++)
            q4[dq] = *(const float4*)&Qr[wrp][dq * 4];

        float s[4];
#pragma unroll
        for (int i = 0; i < 4; i++) {
            int j = lane + i * 32;
            if (j < NTOK) {
                const float4* kp = (const float4*)&Ks[j * KSTR];
                float a0 = 0.0f, a1 = 0.0f;
#pragma unroll
                for (int dq = 0; dq < 8; dq += 2) {
                    float4 k0 = kp[dq], k1 = kp[dq + 1];
                    a0 += q4[dq].x * k0.x + q4[dq].y * k0.y
                        + q4[dq].z * k0.z + q4[dq].w * k0.w;
                    a1 += q4[dq + 1].x * k1.x + q4[dq + 1].y * k1.y
                        + q4[dq + 1].z * k1.z + q4[dq + 1].w * k1.w;
                }
                int   ridx = __ldg(&rel_index[r * NTOK + j]);
                float bia  = __ldg(&rel_table[ridx * NHEAD + h]);
                s[i] = (a0 + a1) * SCALE + bia + __ldg(&maskw[r * NTOK + j]);
            } else {
                s[i] = -1e30f;
            }
        }

        float mx = fmaxf(fmaxf(s[0], s[1]), fmaxf(s[2], s[3]));
#pragma unroll
        for (int o = 16; o > 0; o >>= 1)
            mx = fmaxf(mx, __shfl_xor_sync(0xffffffffu, mx, o));

        float p[4];
        float sum = 0.0f;
#pragma unroll
        for (int i = 0; i < 4; i++) {
            p[i] = __expf(s[i] - mx);
            sum += p[i];
        }
#pragma unroll
        for (int o = 16; o > 0; o >>= 1)
            sum += __shfl_xor_sync(0xffffffffu, sum, o);
        float inv = 1.0f / sum;

#pragma unroll
        for (int i = 0; i < 4; i++) {
            int j = lane + i * 32;
            if (j < NTOK) Ps[wrp][j] = p[i] * inv;
        }
        __syncwarp();

        float o0 = 0.0f, o1 = 0.0f;
#pragma unroll 7
        for (int j = 0; j < 98; j += 2) {
            o0 += Ps[wrp][j]     * Vs[j * KSTR + lane];
            o1 += Ps[wrp][j + 1] * Vs[(j + 1) * KSTR + lane];
        }
        out[((size_t)b * NTOK + r) * DIMC + h * HD + lane] = o0 + o1;
        __syncwarp();
    }
}

// ------------------------- launch ------------------------------------------

extern "C" void kernel_launch(void* const* d_in, const int* in_sizes, int n_in,
                              void* d_out, int out_size)
{
    const float* x         = (const float*)d_in[0];
    const float* mask      = (const float*)d_in[1];
    const float* qkv_w     = (const float*)d_in[2];
    const float* qkv_b     = (const float*)d_in[3];
    const float* rel_table = (const float*)d_in[4];
    const int*   rel_index = (const int*)  d_in[5];
    float* out = (float*)d_out;

    prep_a<<<(GM * GK + 255) / 256, 256>>>(x);
    prep_b<<<(GN * GK + 255) / 256, 256>>>(qkv_w);

    cudaFuncSetAttribute(qkv_mma, cudaFuncAttributeMaxDynamicSharedMemorySize,
                         SMEM_TOTAL);
    dim3 g1(GN / 128, GM / 128);    // (18, 196)
    qkv_mma<<<g1, 256, SMEM_TOTAL>>>(qkv_b);

    dim3 g2(NHEAD, B_);
    attn_kernel<<<g2, 128>>>(mask, rel_table, rel_index, out);
}

// round 4
// speedup vs baseline: 2.7393x; 1.7053x over previous
#include <cuda_runtime.h>
#include <cuda_fp16.h>
#include <math.h>
#include <stdint.h>

// ---------------------------------------------------------------------------
// WindowAttention (Swin): B_=256, N=98, DIM=768, NH=24, HD=32, NW=64
// Phase 1: QKV GEMM, mma.sync fp16 2-term split (A=[hi|lo], B=hi), K'=1536
// Phase 2: tensor-core attention, one CTA per (b,h), S and PV on HMMA
// ---------------------------------------------------------------------------

#define B_    256
#define NTOK  98
#define DIMC  768
#define NHEAD 24
#define HD    32
#define NWIN  64
#define SCALE 0.17677669529663687f

#define GM (B_ * NTOK)     // 25088
#define GK DIMC            // 768
#define GN (3 * DIMC)      // 2304
#define KPA (2 * GK)       // 1536 (A split: [hi | lo])

// Scratch
__device__ __half g_asp[(size_t)GM * KPA];     // x split
__device__ __half g_bh[(size_t)GN * GK];       // w hi
__device__ __half g_qh[B_ * NHEAD * NTOK * HD];
__device__ __half g_ql[B_ * NHEAD * NTOK * HD];
__device__ __half g_kh[B_ * NHEAD * NTOK * HD];
__device__ __half g_vh[B_ * NHEAD * NTOK * HD];

// ---------------- helpers ---------------------------------------------------

__device__ __forceinline__ uint32_t smem_u32(const void* p) {
    uint32_t a;
    asm("{ .reg .u64 t; cvta.to.shared.u64 t, %1; cvt.u32.u64 %0, t; }" : "=r"(a) : "l"(p));
    return a;
}
#define CP16(dst, src) \
    asm volatile("cp.async.cg.shared.global [%0], [%1], 16;" :: "r"(dst), "l"(src) : "memory")
#define CP_COMMIT() asm volatile("cp.async.commit_group;" ::: "memory")
#define CP_WAIT(n)  asm volatile("cp.async.wait_group %0;" :: "n"(n) : "memory")

__device__ __forceinline__ void ldm_x4(uint32_t& r0, uint32_t& r1, uint32_t& r2,
                                       uint32_t& r3, uint32_t addr) {
    asm volatile("ldmatrix.sync.aligned.m8n8.x4.shared.b16 {%0,%1,%2,%3}, [%4];"
                 : "=r"(r0), "=r"(r1), "=r"(r2), "=r"(r3) : "r"(addr));
}
__device__ __forceinline__ void ldm_x4_t(uint32_t& r0, uint32_t& r1, uint32_t& r2,
                                         uint32_t& r3, uint32_t addr) {
    asm volatile("ldmatrix.sync.aligned.m8n8.x4.trans.shared.b16 {%0,%1,%2,%3}, [%4];"
                 : "=r"(r0), "=r"(r1), "=r"(r2), "=r"(r3) : "r"(addr));
}
__device__ __forceinline__ void mma_f16(float* c, const uint32_t* a, uint32_t b0, uint32_t b1) {
    asm volatile(
        "mma.sync.aligned.m16n8k16.row.col.f32.f16.f16.f32 "
        "{%0,%1,%2,%3}, {%4,%5,%6,%7}, {%8,%9}, {%0,%1,%2,%3};"
        : "+f"(c[0]), "+f"(c[1]), "+f"(c[2]), "+f"(c[3])
        : "r"(a[0]), "r"(a[1]), "r"(a[2]), "r"(a[3]), "r"(b0), "r"(b1));
}
__device__ __forceinline__ uint32_t pack_h2(__half a, __half b) {
    __half2 h = __halves2half2(a, b);
    return *reinterpret_cast<uint32_t*>(&h);
}

// ---------------- split-precision prep -------------------------------------

__global__ __launch_bounds__(256) void prep_a(const float* __restrict__ x) {
    int i = blockIdx.x * 256 + threadIdx.x;
    if (i >= GM * GK) return;
    int r = i / GK, k = i - r * GK;
    float f = x[i];
    __half hi = __float2half_rn(f);
    __half lo = __float2half_rn(f - __half2float(hi));
    size_t base = (size_t)r * KPA + k;
    g_asp[base]      = hi;
    g_asp[base + GK] = lo;
}

__global__ __launch_bounds__(256) void prep_b(const float* __restrict__ w) {
    int i = blockIdx.x * 256 + threadIdx.x;
    if (i >= GN * GK) return;
    g_bh[i] = __float2half_rn(w[i]);
}

// ---------------- QKV GEMM (mma.sync fp16) ----------------------------------
// BM=BN=128, BK=64, 8 warps (2m x 4n), 3-stage cp.async.
// A: K'=1536 (24 chunks); B: K=768, chunk bc = c % 12.

#define NSTAGE 3
#define CHUNKS 24
#define STAGE_BYTES 32768
#define SMEM_TOTAL (NSTAGE * STAGE_BYTES)

__global__ __launch_bounds__(256) void qkv_mma(const float* __restrict__ bias)
{
    extern __shared__ __align__(128) char smem[];
    const uint32_t sb = smem_u32(smem);

    const int tid  = threadIdx.x;
    const int lane = tid & 31;
    const int wid  = tid >> 5;
    const int wm   = wid & 1;
    const int wn   = wid >> 1;

    const int m0 = blockIdx.y * 128;
    const int c0 = blockIdx.x * 128;

    const __half* agbase = g_asp + (size_t)m0 * KPA;
    const __half* bgbase = g_bh + (size_t)c0 * GK;

    int arow[4], akc[4];
#pragma unroll
    for (int l = 0; l < 4; l++) {
        int ci = tid + l * 256;
        arow[l] = ci >> 3;
        akc[l]  = ci & 7;
    }

    const int sub  = lane >> 3;
    const int lr   = (lane & 7) + ((sub & 1) << 3);
    const int subh = sub >> 1;

    uint32_t a_rowoff[4];
    int      a_rx[4];
#pragma unroll
    for (int i = 0; i < 4; i++) {
        int row = wm * 64 + i * 16 + lr;
        a_rowoff[i] = (uint32_t)row * 128;
        a_rx[i]     = row & 7;
    }
    uint32_t b_rowoff[2];
    int      b_rx[2];
#pragma unroll
    for (int g = 0; g < 2; g++) {
        int row = wn * 32 + g * 16 + lr;
        b_rowoff[g] = (uint32_t)row * 128;
        b_rx[g]     = row & 7;
    }

    float acc[4][4][4];
#pragma unroll
    for (int i = 0; i < 4; i++)
#pragma unroll
        for (int j = 0; j < 4; j++)
#pragma unroll
            for (int q = 0; q < 4; q++) acc[i][j][q] = 0.0f;

#pragma unroll
    for (int c = 0; c < 2; c++) {
        uint32_t aB = sb + c * STAGE_BYTES;
        uint32_t bB = aB + 16384;
#pragma unroll
        for (int l = 0; l < 4; l++) {
            int r = arow[l], kc = akc[l];
            CP16(aB + r * 128 + ((kc ^ (r & 7)) << 4),
                 agbase + (size_t)r * KPA + c * 64 + kc * 8);
            CP16(bB + r * 128 + ((kc ^ (r & 7)) << 4),
                 bgbase + (size_t)r * GK + c * 64 + kc * 8);
        }
        CP_COMMIT();
    }

#pragma unroll 1
    for (int c = 0; c < CHUNKS; c++) {
        if (c + 2 < CHUNKS) {
            int cs = c + 2;
            int bcs = (cs >= 12) ? cs - 12 : cs;
            uint32_t aB = sb + (cs % NSTAGE) * STAGE_BYTES;
            uint32_t bB = aB + 16384;
#pragma unroll
            for (int l = 0; l < 4; l++) {
                int r = arow[l], kc = akc[l];
                CP16(aB + r * 128 + ((kc ^ (r & 7)) << 4),
                     agbase + (size_t)r * KPA + cs * 64 + kc * 8);
                CP16(bB + r * 128 + ((kc ^ (r & 7)) << 4),
                     bgbase + (size_t)r * GK + bcs * 64 + kc * 8);
            }
        }
        CP_COMMIT();
        CP_WAIT(2);
        __syncthreads();

        const uint32_t aB = sb + (c % NSTAGE) * STAGE_BYTES;
        const uint32_t bB = aB + 16384;

#pragma unroll
        for (int j = 0; j < 4; j++) {
            uint32_t af[4][4];
#pragma unroll
            for (int i = 0; i < 4; i++) {
                uint32_t addr = aB + a_rowoff[i]
                              + (uint32_t)(((j * 2 + subh) ^ a_rx[i]) << 4);
                ldm_x4(af[i][0], af[i][1], af[i][2], af[i][3], addr);
            }
            uint32_t bf[4][2];
#pragma unroll
            for (int g = 0; g < 2; g++) {
                uint32_t r0, r1, r2, r3;
                uint32_t addr = bB + b_rowoff[g]
                              + (uint32_t)(((j * 2 + subh) ^ b_rx[g]) << 4);
                ldm_x4(r0, r1, r2, r3, addr);
                bf[2 * g][0]     = r0; bf[2 * g][1]     = r2;
                bf[2 * g + 1][0] = r1; bf[2 * g + 1][1] = r3;
            }
#pragma unroll
            for (int i = 0; i < 4; i++)
#pragma unroll
                for (int n = 0; n < 4; n++)
                    mma_f16(acc[i][n], af[i], bf[n][0], bf[n][1]);
        }
        __syncthreads();
    }

    // Epilogue: bias, fold SCALE into Q, split Q hi/lo fp16, K/V single fp16.
    const int rbase = lane >> 2;
    const int cpair = lane & 3;
#pragma unroll
    for (int i = 0; i < 4; i++) {
#pragma unroll
        for (int half = 0; half < 2; half++) {
            int m = m0 + wm * 64 + i * 16 + rbase + half * 8;
            int b = m / NTOK;
            int tok = m - b * NTOK;
            size_t obase = (size_t)b * NHEAD * NTOK * HD + (size_t)tok * HD;
#pragma unroll
            for (int n = 0; n < 4; n++) {
#pragma unroll
                for (int e = 0; e < 2; e++) {
                    int cc = c0 + wn * 32 + n * 8 + cpair * 2 + e;
                    float v = acc[i][n][half * 2 + e] + __ldg(&bias[cc]);
                    int s3 = cc % 3;
                    int d  = (cc / 3) & 31;
                    int h  = cc / 96;
                    size_t dst = obase + (size_t)h * NTOK * HD + d;
                    if (s3 == 0) {
                        float vq = v * SCALE;
                        __half hh = __float2half_rn(vq);
                        g_qh[dst] = hh;
                        g_ql[dst] = __float2half_rn(vq - __half2float(hh));
                    } else if (s3 == 1) {
                        g_kh[dst] = __float2half_rn(v);
                    } else {
                        g_vh[dst] = __float2half_rn(v);
                    }
                }
            }
        }
    }
}

// ---------------- tensor-core attention -------------------------------------
// CTA = (h, b). 4 warps. Rows/keys padded 98 -> 112. Row stride 80B in smem.
// Warp w handles m16 tiles {w, w+4} (7 tiles total).

#define RSTR 40   // halfs per row (80 bytes)

__global__ __launch_bounds__(128) void attn_tc(
    const float* __restrict__ mask,
    const float* __restrict__ rel_table,
    const int*   __restrict__ rel_index,
    float* __restrict__ out)
{
    __shared__ __align__(16) __half sQh[112 * RSTR];
    __shared__ __align__(16) __half sQl[112 * RSTR];
    __shared__ __align__(16) __half sKh[112 * RSTR];
    __shared__ __align__(16) __half sVh[112 * RSTR];

    const int h    = blockIdx.x;
    const int b    = blockIdx.y;
    const int tid  = threadIdx.x;
    const int lane = tid & 31;
    const int w    = tid >> 5;
    const int g    = lane >> 2;   // row group
    const int t    = lane & 3;    // col pair

    const size_t gbase = ((size_t)b * NHEAD + h) * NTOK * HD;
    const uint32_t qhB = smem_u32(sQh);
    const uint32_t qlB = smem_u32(sQl);
    const uint32_t khB = smem_u32(sKh);
    const uint32_t vhB = smem_u32(sVh);

    // zero pad rows 98..111 (first 64B of each row)
    for (int idx = tid; idx < 14 * 4; idx += 128) {
        int row = 98 + (idx >> 2);
        int q   = idx & 3;
        uint4 z = {0, 0, 0, 0};
        *(uint4*)((char*)sQh + row * 80 + q * 16) = z;
        *(uint4*)((char*)sQl + row * 80 + q * 16) = z;
        *(uint4*)((char*)sKh + row * 80 + q * 16) = z;
        *(uint4*)((char*)sVh + row * 80 + q * 16) = z;
    }
    // stage Q/K/V
    for (int idx = tid; idx < 98 * 4; idx += 128) {
        int row = idx >> 2;
        int q   = idx & 3;
        size_t src = gbase + row * 32 + q * 8;
        uint32_t doff = row * 80 + q * 16;
        CP16(qhB + doff, g_qh + src);
        CP16(qlB + doff, g_ql + src);
        CP16(khB + doff, g_kh + src);
        CP16(vhB + doff, g_vh + src);
    }
    CP_COMMIT();
    CP_WAIT(0);
    __syncthreads();

    const float* maskw = mask + (size_t)(b & (NWIN - 1)) * NTOK * NTOK;

#pragma unroll 1
    for (int mi = 0; mi < 2; mi++) {
        int mt = w + mi * 4;
        if (mt > 6) break;
        const int r0 = mt * 16;

        // ---- Q fragments (2 k16 tiles, hi and lo) --------------------------
        uint32_t qh[2][4], ql[2][4];
        {
            int qrow = r0 + (lane & 7) + (((lane >> 3) & 1) << 3);
            int qcol = ((lane >> 4) << 3);
#pragma unroll
            for (int kt = 0; kt < 2; kt++) {
                uint32_t off = (uint32_t)qrow * 80 + (uint32_t)(kt * 16 + qcol) * 2;
                ldm_x4(qh[kt][0], qh[kt][1], qh[kt][2], qh[kt][3], qhB + off);
                ldm_x4(ql[kt][0], ql[kt][1], ql[kt][2], ql[kt][3], qlB + off);
            }
        }

        // ---- S = Q K^T ------------------------------------------------------
        float sc[14][4];
#pragma unroll
        for (int i = 0; i < 14; i++)
#pragma unroll
            for (int q = 0; q < 4; q++) sc[i][q] = 0.0f;

        {
            int krow = (lane & 7) + ((lane >> 4) << 3);
            int kcol = ((lane >> 3) & 1) << 3;
#pragma unroll
            for (int nt2 = 0; nt2 < 7; nt2++) {
                int j0 = nt2 * 16;
                uint32_t k0[4], k1[4];
                uint32_t roff = (uint32_t)(j0 + krow) * 80;
                ldm_x4(k0[0], k0[1], k0[2], k0[3], khB + roff + (uint32_t)(kcol) * 2);
                ldm_x4(k1[0], k1[1], k1[2], k1[3], khB + roff + (uint32_t)(16 + kcol) * 2);
                float* aA = sc[2 * nt2];
                float* aB = sc[2 * nt2 + 1];
                mma_f16(aA, qh[0], k0[0], k0[1]);
                mma_f16(aA, qh[1], k1[0], k1[1]);
                mma_f16(aA, ql[0], k0[0], k0[1]);
                mma_f16(aA, ql[1], k1[0], k1[1]);
                mma_f16(aB, qh[0], k0[2], k0[3]);
                mma_f16(aB, qh[1], k1[2], k1[3]);
                mma_f16(aB, ql[0], k0[2], k0[3]);
                mma_f16(aB, ql[1], k1[2], k1[3]);
            }
        }

        // ---- bias + mask + softmax (registers only) -------------------------
#pragma unroll
        for (int h2 = 0; h2 < 2; h2++) {
            int row = r0 + g + h2 * 8;
            float mx = -1e30f;
            bool rok = (row < NTOK);
#pragma unroll
            for (int i = 0; i < 14; i++) {
                int jc = 8 * i + 2 * t;
                float s0, s1;
                if (rok && jc < NTOK) {
                    float2 mk = *(const float2*)(maskw + row * NTOK + jc);
                    int2   id = *(const int2*)(rel_index + row * NTOK + jc);
                    s0 = sc[i][h2 * 2]     + mk.x + __ldg(rel_table + id.x * NHEAD + h);
                    s1 = sc[i][h2 * 2 + 1] + mk.y + __ldg(rel_table + id.y * NHEAD + h);
                } else {
                    s0 = -1e30f; s1 = -1e30f;
                }
                sc[i][h2 * 2]     = s0;
                sc[i][h2 * 2 + 1] = s1;
                mx = fmaxf(mx, fmaxf(s0, s1));
            }
            mx = fmaxf(mx, __shfl_xor_sync(0xffffffffu, mx, 1));
            mx = fmaxf(mx, __shfl_xor_sync(0xffffffffu, mx, 2));
            float sum = 0.0f;
#pragma unroll
            for (int i = 0; i < 14; i++) {
                float p0 = __expf(sc[i][h2 * 2]     - mx);
                float p1 = __expf(sc[i][h2 * 2 + 1] - mx);
                sc[i][h2 * 2]     = p0;
                sc[i][h2 * 2 + 1] = p1;
                sum += p0 + p1;
            }
            sum += __shfl_xor_sync(0xffffffffu, sum, 1);
            sum += __shfl_xor_sync(0xffffffffu, sum, 2);
            float inv = 1.0f / sum;
#pragma unroll
            for (int i = 0; i < 14; i++) {
                sc[i][h2 * 2]     *= inv;
                sc[i][h2 * 2 + 1] *= inv;
            }
        }

        // ---- O = P V --------------------------------------------------------
        float o[4][4];
#pragma unroll
        for (int n = 0; n < 4; n++)
#pragma unroll
            for (int q = 0; q < 4; q++) o[n][q] = 0.0f;

        {
            int vrow = (lane & 7) + (((lane >> 3) & 1) << 3);
            int vcol = (lane >> 4) << 3;
#pragma unroll
            for (int kk = 0; kk < 7; kk++) {
                // P fragments (hi/lo) from sc registers
                uint32_t ph[4], pl[4];
#pragma unroll
                for (int q = 0; q < 4; q++) {
                    float p0 = sc[2 * kk + (q >> 1)][(q & 1) * 2];
                    float p1 = sc[2 * kk + (q >> 1)][(q & 1) * 2 + 1];
                    // q order must be: a0=(g,2t) tile even, a1=(g+8) tile even,
                    // a2=(g) tile odd, a3=(g+8) tile odd
                    (void)p0; (void)p1;
                }
                {
                    float e0 = sc[2 * kk][0],     e1 = sc[2 * kk][1];
                    float e2 = sc[2 * kk][2],     e3 = sc[2 * kk][3];
                    float e4 = sc[2 * kk + 1][0], e5 = sc[2 * kk + 1][1];
                    float e6 = sc[2 * kk + 1][2], e7 = sc[2 * kk + 1][3];
                    __half h0 = __float2half_rn(e0), h1 = __float2half_rn(e1);
                    __half h2 = __float2half_rn(e2), h3 = __float2half_rn(e3);
                    __half h4 = __float2half_rn(e4), h5 = __float2half_rn(e5);
                    __half h6 = __float2half_rn(e6), h7 = __float2half_rn(e7);
                    ph[0] = pack_h2(h0, h1);
                    ph[1] = pack_h2(h2, h3);
                    ph[2] = pack_h2(h4, h5);
                    ph[3] = pack_h2(h6, h7);
                    pl[0] = pack_h2(__float2half_rn(e0 - __half2float(h0)),
                                    __float2half_rn(e1 - __half2float(h1)));
                    pl[1] = pack_h2(__float2half_rn(e2 - __half2float(h2)),
                                    __float2half_rn(e3 - __half2float(h3)));
                    pl[2] = pack_h2(__float2half_rn(e4 - __half2float(h4)),
                                    __float2half_rn(e5 - __half2float(h5)));
                    pl[3] = pack_h2(__float2half_rn(e6 - __half2float(h6)),
                                    __float2half_rn(e7 - __half2float(h7)));
                }
                int j0 = kk * 16;
                uint32_t v0[4], v16[4];
                uint32_t roff = (uint32_t)(j0 + vrow) * 80;
                ldm_x4_t(v0[0], v0[1], v0[2], v0[3],  vhB + roff + (uint32_t)vcol * 2);
                ldm_x4_t(v16[0], v16[1], v16[2], v16[3],
                         vhB + roff + (uint32_t)(16 + vcol) * 2);
                mma_f16(o[0], ph, v0[0], v0[1]);
                mma_f16(o[1], ph, v0[2], v0[3]);
                mma_f16(o[2], ph, v16[0], v16[1]);
                mma_f16(o[3], ph, v16[2], v16[3]);
                mma_f16(o[0], pl, v0[0], v0[1]);
                mma_f16(o[1], pl, v0[2], v0[3]);
                mma_f16(o[2], pl, v16[0], v16[1]);
                mma_f16(o[3], pl, v16[2], v16[3]);
            }
        }

        // ---- store ----------------------------------------------------------
        {
            int rowA = r0 + g;
            int rowB = rowA + 8;
            if (rowA < NTOK) {
                float* dst = out + ((size_t)b * NTOK + rowA) * DIMC + h * HD;
#pragma unroll
                for (int n = 0; n < 4; n++) {
                    float2 v = {o[n][0], o[n][1]};
                    *(float2*)(dst + n * 8 + 2 * t) = v;
                }
            }
            if (rowB < NTOK) {
                float* dst = out + ((size_t)b * NTOK + rowB) * DIMC + h * HD;
#pragma unroll
                for (int n = 0; n < 4; n++) {
                    float2 v = {o[n][2], o[n][3]};
                    *(float2*)(dst + n * 8 + 2 * t) = v;
                }
            }
        }
    }
}

// ------------------------- launch ------------------------------------------

extern "C" void kernel_launch(void* const* d_in, const int* in_sizes, int n_in,
                              void* d_out, int out_size)
{
    const float* x         = (const float*)d_in[0];
    const float* mask      = (const float*)d_in[1];
    const float* qkv_w     = (const float*)d_in[2];
    const float* qkv_b     = (const float*)d_in[3];
    const float* rel_table = (const float*)d_in[4];
    const int*   rel_index = (const int*)  d_in[5];
    float* out = (float*)d_out;

    prep_a<<<(GM * GK + 255) / 256, 256>>>(x);
    prep_b<<<(GN * GK + 255) / 256, 256>>>(qkv_w);

    cudaFuncSetAttribute(qkv_mma, cudaFuncAttributeMaxDynamicSharedMemorySize,
                         SMEM_TOTAL);
    dim3 g1(GN / 128, GM / 128);    // (18, 196)
    qkv_mma<<<g1, 256, SMEM_TOTAL>>>(qkv_b);

    dim3 g2(NHEAD, B_);             // (24, 256)
    attn_tc<<<g2, 128>>>(mask, rel_table, rel_index, out);
}

// round 5
// speedup vs baseline: 4.4337x; 1.6185x over previous
#include <cuda_runtime.h>
#include <cuda_fp16.h>
#include <math.h>
#include <stdint.h>

// ---------------------------------------------------------------------------
// WindowAttention (Swin): B_=256, N=98, DIM=768, NH=24, HD=32, NW=64
// Phase 1: QKV GEMM, mma.sync single fp16 (K=768)
// Phase 2: tensor-core attention (Q 2-split, P 2-split), fused bias table
// ---------------------------------------------------------------------------

#define B_    256
#define NTOK  98
#define DIMC  768
#define NHEAD 24
#define HD    32
#define NWIN  64
#define SCALE 0.17677669529663687f

#define GM (B_ * NTOK)     // 25088
#define GK DIMC            // 768
#define GN (3 * DIMC)      // 2304

// Scratch
__device__ __half g_asp[(size_t)GM * GK];      // x fp16
__device__ __half g_bh[(size_t)GN * GK];       // w fp16
__device__ __half g_qh[B_ * NHEAD * NTOK * HD];
__device__ __half g_ql[B_ * NHEAD * NTOK * HD];
__device__ __half g_kh[B_ * NHEAD * NTOK * HD];
__device__ __half g_vh[B_ * NHEAD * NTOK * HD];
__device__ float  g_bias[NHEAD * NTOK * NTOK]; // fused rel-pos bias [h][r][j]

// ---------------- helpers ---------------------------------------------------

__device__ __forceinline__ uint32_t smem_u32(const void* p) {
    uint32_t a;
    asm("{ .reg .u64 t; cvta.to.shared.u64 t, %1; cvt.u32.u64 %0, t; }" : "=r"(a) : "l"(p));
    return a;
}
#define CP16(dst, src) \
    asm volatile("cp.async.cg.shared.global [%0], [%1], 16;" :: "r"(dst), "l"(src) : "memory")
#define CP_COMMIT() asm volatile("cp.async.commit_group;" ::: "memory")
#define CP_WAIT(n)  asm volatile("cp.async.wait_group %0;" :: "n"(n) : "memory")

__device__ __forceinline__ void ldm_x4(uint32_t& r0, uint32_t& r1, uint32_t& r2,
                                       uint32_t& r3, uint32_t addr) {
    asm volatile("ldmatrix.sync.aligned.m8n8.x4.shared.b16 {%0,%1,%2,%3}, [%4];"
                 : "=r"(r0), "=r"(r1), "=r"(r2), "=r"(r3) : "r"(addr));
}
__device__ __forceinline__ void ldm_x4_t(uint32_t& r0, uint32_t& r1, uint32_t& r2,
                                         uint32_t& r3, uint32_t addr) {
    asm volatile("ldmatrix.sync.aligned.m8n8.x4.trans.shared.b16 {%0,%1,%2,%3}, [%4];"
                 : "=r"(r0), "=r"(r1), "=r"(r2), "=r"(r3) : "r"(addr));
}
__device__ __forceinline__ void mma_f16(float* c, const uint32_t* a, uint32_t b0, uint32_t b1) {
    asm volatile(
        "mma.sync.aligned.m16n8k16.row.col.f32.f16.f16.f32 "
        "{%0,%1,%2,%3}, {%4,%5,%6,%7}, {%8,%9}, {%0,%1,%2,%3};"
        : "+f"(c[0]), "+f"(c[1]), "+f"(c[2]), "+f"(c[3])
        : "r"(a[0]), "r"(a[1]), "r"(a[2]), "r"(a[3]), "r"(b0), "r"(b1));
}
__device__ __forceinline__ uint32_t pack_h2(__half a, __half b) {
    __half2 h = __halves2half2(a, b);
    return *reinterpret_cast<uint32_t*>(&h);
}

// ---------------- prep kernels ----------------------------------------------

__global__ __launch_bounds__(256) void prep_a(const float* __restrict__ x) {
    int i = blockIdx.x * 256 + threadIdx.x;
    if (i < GM * GK) g_asp[i] = __float2half_rn(x[i]);
}
__global__ __launch_bounds__(256) void prep_b(const float* __restrict__ w) {
    int i = blockIdx.x * 256 + threadIdx.x;
    if (i < GN * GK) g_bh[i] = __float2half_rn(w[i]);
}
__global__ __launch_bounds__(256) void prep_bias(
    const float* __restrict__ rel_table, const int* __restrict__ rel_index)
{
    int i = blockIdx.x * 256 + threadIdx.x;
    if (i >= NHEAD * NTOK * NTOK) return;
    int h  = i / (NTOK * NTOK);
    int rj = i - h * (NTOK * NTOK);
    g_bias[i] = __ldg(rel_table + __ldg(rel_index + rj) * NHEAD + h);
}

// ---------------- QKV GEMM (mma.sync fp16) ----------------------------------
// BM=BN=128, BK=64, 8 warps (2m x 4n), 3-stage cp.async, K=768 (12 chunks).

#define NSTAGE 3
#define CHUNKS 12
#define STAGE_BYTES 32768
#define SMEM_TOTAL (NSTAGE * STAGE_BYTES)

__global__ __launch_bounds__(256) void qkv_mma(const float* __restrict__ bias)
{
    extern __shared__ __align__(128) char smem[];
    const uint32_t sb = smem_u32(smem);

    const int tid  = threadIdx.x;
    const int lane = tid & 31;
    const int wid  = tid >> 5;
    const int wm   = wid & 1;
    const int wn   = wid >> 1;

    const int m0 = blockIdx.y * 128;
    const int c0 = blockIdx.x * 128;

    const __half* agbase = g_asp + (size_t)m0 * GK;
    const __half* bgbase = g_bh + (size_t)c0 * GK;

    int arow[4], akc[4];
#pragma unroll
    for (int l = 0; l < 4; l++) {
        int ci = tid + l * 256;
        arow[l] = ci >> 3;
        akc[l]  = ci & 7;
    }

    const int sub  = lane >> 3;
    const int lr   = (lane & 7) + ((sub & 1) << 3);
    const int subh = sub >> 1;

    uint32_t a_rowoff[4];
    int      a_rx[4];
#pragma unroll
    for (int i = 0; i < 4; i++) {
        int row = wm * 64 + i * 16 + lr;
        a_rowoff[i] = (uint32_t)row * 128;
        a_rx[i]     = row & 7;
    }
    uint32_t b_rowoff[2];
    int      b_rx[2];
#pragma unroll
    for (int g = 0; g < 2; g++) {
        int row = wn * 32 + g * 16 + lr;
        b_rowoff[g] = (uint32_t)row * 128;
        b_rx[g]     = row & 7;
    }

    float acc[4][4][4];
#pragma unroll
    for (int i = 0; i < 4; i++)
#pragma unroll
        for (int j = 0; j < 4; j++)
#pragma unroll
            for (int q = 0; q < 4; q++) acc[i][j][q] = 0.0f;

#pragma unroll
    for (int c = 0; c < 2; c++) {
        uint32_t aB = sb + c * STAGE_BYTES;
        uint32_t bB = aB + 16384;
#pragma unroll
        for (int l = 0; l < 4; l++) {
            int r = arow[l], kc = akc[l];
            CP16(aB + r * 128 + ((kc ^ (r & 7)) << 4),
                 agbase + (size_t)r * GK + c * 64 + kc * 8);
            CP16(bB + r * 128 + ((kc ^ (r & 7)) << 4),
                 bgbase + (size_t)r * GK + c * 64 + kc * 8);
        }
        CP_COMMIT();
    }

#pragma unroll 1
    for (int c = 0; c < CHUNKS; c++) {
        if (c + 2 < CHUNKS) {
            int cs = c + 2;
            uint32_t aB = sb + (cs % NSTAGE) * STAGE_BYTES;
            uint32_t bB = aB + 16384;
#pragma unroll
            for (int l = 0; l < 4; l++) {
                int r = arow[l], kc = akc[l];
                CP16(aB + r * 128 + ((kc ^ (r & 7)) << 4),
                     agbase + (size_t)r * GK + cs * 64 + kc * 8);
                CP16(bB + r * 128 + ((kc ^ (r & 7)) << 4),
                     bgbase + (size_t)r * GK + cs * 64 + kc * 8);
            }
        }
        CP_COMMIT();
        CP_WAIT(2);
        __syncthreads();

        const uint32_t aB = sb + (c % NSTAGE) * STAGE_BYTES;
        const uint32_t bB = aB + 16384;

#pragma unroll
        for (int j = 0; j < 4; j++) {
            uint32_t af[4][4];
#pragma unroll
            for (int i = 0; i < 4; i++) {
                uint32_t addr = aB + a_rowoff[i]
                              + (uint32_t)(((j * 2 + subh) ^ a_rx[i]) << 4);
                ldm_x4(af[i][0], af[i][1], af[i][2], af[i][3], addr);
            }
            uint32_t bf[4][2];
#pragma unroll
            for (int g = 0; g < 2; g++) {
                uint32_t r0, r1, r2, r3;
                uint32_t addr = bB + b_rowoff[g]
                              + (uint32_t)(((j * 2 + subh) ^ b_rx[g]) << 4);
                ldm_x4(r0, r1, r2, r3, addr);
                bf[2 * g][0]     = r0; bf[2 * g][1]     = r2;
                bf[2 * g + 1][0] = r1; bf[2 * g + 1][1] = r3;
            }
#pragma unroll
            for (int i = 0; i < 4; i++)
#pragma unroll
                for (int n = 0; n < 4; n++)
                    mma_f16(acc[i][n], af[i], bf[n][0], bf[n][1]);
        }
        __syncthreads();
    }

    // Epilogue: bias, fold SCALE into Q, split Q hi/lo fp16, K/V single fp16.
    const int rbase = lane >> 2;
    const int cpair = lane & 3;
#pragma unroll
    for (int i = 0; i < 4; i++) {
#pragma unroll
        for (int half = 0; half < 2; half++) {
            int m = m0 + wm * 64 + i * 16 + rbase + half * 8;
            int b = m / NTOK;
            int tok = m - b * NTOK;
            size_t obase = (size_t)b * NHEAD * NTOK * HD + (size_t)tok * HD;
#pragma unroll
            for (int n = 0; n < 4; n++) {
#pragma unroll
                for (int e = 0; e < 2; e++) {
                    int cc = c0 + wn * 32 + n * 8 + cpair * 2 + e;
                    float v = acc[i][n][half * 2 + e] + __ldg(&bias[cc]);
                    int s3 = cc % 3;
                    int d  = (cc / 3) & 31;
                    int h  = cc / 96;
                    size_t dst = obase + (size_t)h * NTOK * HD + d;
                    if (s3 == 0) {
                        float vq = v * SCALE;
                        __half hh = __float2half_rn(vq);
                        g_qh[dst] = hh;
                        g_ql[dst] = __float2half_rn(vq - __half2float(hh));
                    } else if (s3 == 1) {
                        g_kh[dst] = __float2half_rn(v);
                    } else {
                        g_vh[dst] = __float2half_rn(v);
                    }
                }
            }
        }
    }
}

// ---------------- tensor-core attention -------------------------------------
// CTA = (h, b). 4 warps. Rows/keys padded 98 -> 112. Row stride 80B in smem.
// Warp w handles m16 tiles {w, w+4} (7 tiles total).

#define RSTR 40   // halfs per row (80 bytes)

__global__ __launch_bounds__(128) void attn_tc(
    const float* __restrict__ mask,
    float* __restrict__ out)
{
    __shared__ __align__(16) __half sQh[112 * RSTR];
    __shared__ __align__(16) __half sQl[112 * RSTR];
    __shared__ __align__(16) __half sKh[112 * RSTR];
    __shared__ __align__(16) __half sVh[112 * RSTR];

    const int h    = blockIdx.x;
    const int b    = blockIdx.y;
    const int tid  = threadIdx.x;
    const int lane = tid & 31;
    const int w    = tid >> 5;
    const int g    = lane >> 2;   // row group
    const int t    = lane & 3;    // col pair

    const size_t gbase = ((size_t)b * NHEAD + h) * NTOK * HD;
    const uint32_t qhB = smem_u32(sQh);
    const uint32_t qlB = smem_u32(sQl);
    const uint32_t khB = smem_u32(sKh);
    const uint32_t vhB = smem_u32(sVh);

    // zero pad rows 98..111
    for (int idx = tid; idx < 14 * 4; idx += 128) {
        int row = 98 + (idx >> 2);
        int q   = idx & 3;
        uint4 z = {0, 0, 0, 0};
        *(uint4*)((char*)sQh + row * 80 + q * 16) = z;
        *(uint4*)((char*)sQl + row * 80 + q * 16) = z;
        *(uint4*)((char*)sKh + row * 80 + q * 16) = z;
        *(uint4*)((char*)sVh + row * 80 + q * 16) = z;
    }
    // stage Q/K/V
    for (int idx = tid; idx < 98 * 4; idx += 128) {
        int row = idx >> 2;
        int q   = idx & 3;
        size_t src = gbase + row * 32 + q * 8;
        uint32_t doff = row * 80 + q * 16;
        CP16(qhB + doff, g_qh + src);
        CP16(qlB + doff, g_ql + src);
        CP16(khB + doff, g_kh + src);
        CP16(vhB + doff, g_vh + src);
    }
    CP_COMMIT();
    CP_WAIT(0);
    __syncthreads();

    const float* maskw = mask + (size_t)(b & (NWIN - 1)) * NTOK * NTOK;
    const float* biash = g_bias + (size_t)h * NTOK * NTOK;

#pragma unroll 1
    for (int mi = 0; mi < 2; mi++) {
        int mt = w + mi * 4;
        if (mt > 6) break;
        const int r0 = mt * 16;

        // ---- Q fragments (2 k16 tiles, hi and lo) --------------------------
        uint32_t qh[2][4], ql[2][4];
        {
            int qrow = r0 + (lane & 7) + (((lane >> 3) & 1) << 3);
            int qcol = ((lane >> 4) << 3);
#pragma unroll
            for (int kt = 0; kt < 2; kt++) {
                uint32_t off = (uint32_t)qrow * 80 + (uint32_t)(kt * 16 + qcol) * 2;
                ldm_x4(qh[kt][0], qh[kt][1], qh[kt][2], qh[kt][3], qhB + off);
                ldm_x4(ql[kt][0], ql[kt][1], ql[kt][2], ql[kt][3], qlB + off);
            }
        }

        // ---- S = Q K^T ------------------------------------------------------
        float sc[14][4];
#pragma unroll
        for (int i = 0; i < 14; i++)
#pragma unroll
            for (int q = 0; q < 4; q++) sc[i][q] = 0.0f;

        {
            int krow = (lane & 7) + ((lane >> 4) << 3);
            int kcol = ((lane >> 3) & 1) << 3;
#pragma unroll
            for (int nt2 = 0; nt2 < 7; nt2++) {
                int j0 = nt2 * 16;
                uint32_t k0[4], k1[4];
                uint32_t roff = (uint32_t)(j0 + krow) * 80;
                ldm_x4(k0[0], k0[1], k0[2], k0[3], khB + roff + (uint32_t)(kcol) * 2);
                ldm_x4(k1[0], k1[1], k1[2], k1[3], khB + roff + (uint32_t)(16 + kcol) * 2);
                float* aA = sc[2 * nt2];
                float* aB = sc[2 * nt2 + 1];
                mma_f16(aA, qh[0], k0[0], k0[1]);
                mma_f16(aA, qh[1], k1[0], k1[1]);
                mma_f16(aA, ql[0], k0[0], k0[1]);
                mma_f16(aA, ql[1], k1[0], k1[1]);
                mma_f16(aB, qh[0], k0[2], k0[3]);
                mma_f16(aB, qh[1], k1[2], k1[3]);
                mma_f16(aB, ql[0], k0[2], k0[3]);
                mma_f16(aB, ql[1], k1[2], k1[3]);
            }
        }

        // ---- bias + mask + softmax (registers only) -------------------------
#pragma unroll
        for (int h2 = 0; h2 < 2; h2++) {
            int row = r0 + g + h2 * 8;
            float mx = -1e30f;
            bool rok = (row < NTOK);
#pragma unroll
            for (int i = 0; i < 14; i++) {
                int jc = 8 * i + 2 * t;
                float s0, s1;
                if (rok && jc < NTOK) {
                    float2 mk = *(const float2*)(maskw + row * NTOK + jc);
                    float2 bi = *(const float2*)(biash + row * NTOK + jc);
                    s0 = sc[i][h2 * 2]     + mk.x + bi.x;
                    s1 = sc[i][h2 * 2 + 1] + mk.y + bi.y;
                } else {
                    s0 = -1e30f; s1 = -1e30f;
                }
                sc[i][h2 * 2]     = s0;
                sc[i][h2 * 2 + 1] = s1;
                mx = fmaxf(mx, fmaxf(s0, s1));
            }
            mx = fmaxf(mx, __shfl_xor_sync(0xffffffffu, mx, 1));
            mx = fmaxf(mx, __shfl_xor_sync(0xffffffffu, mx, 2));
            float sum = 0.0f;
#pragma unroll
            for (int i = 0; i < 14; i++) {
                float p0 = __expf(sc[i][h2 * 2]     - mx);
                float p1 = __expf(sc[i][h2 * 2 + 1] - mx);
                sc[i][h2 * 2]     = p0;
                sc[i][h2 * 2 + 1] = p1;
                sum += p0 + p1;
            }
            sum += __shfl_xor_sync(0xffffffffu, sum, 1);
            sum += __shfl_xor_sync(0xffffffffu, sum, 2);
            float inv = 1.0f / sum;
#pragma unroll
            for (int i = 0; i < 14; i++) {
                sc[i][h2 * 2]     *= inv;
                sc[i][h2 * 2 + 1] *= inv;
            }
        }

        // ---- O = P V --------------------------------------------------------
        float o[4][4];
#pragma unroll
        for (int n = 0; n < 4; n++)
#pragma unroll
            for (int q = 0; q < 4; q++) o[n][q] = 0.0f;

        {
            int vrow = (lane & 7) + (((lane >> 3) & 1) << 3);
            int vcol = (lane >> 4) << 3;
#pragma unroll
            for (int kk = 0; kk < 7; kk++) {
                uint32_t ph[4], pl[4];
                {
                    float e0 = sc[2 * kk][0],     e1 = sc[2 * kk][1];
                    float e2 = sc[2 * kk][2],     e3 = sc[2 * kk][3];
                    float e4 = sc[2 * kk + 1][0], e5 = sc[2 * kk + 1][1];
                    float e6 = sc[2 * kk + 1][2], e7 = sc[2 * kk + 1][3];
                    __half h0 = __float2half_rn(e0), h1 = __float2half_rn(e1);
                    __half h2 = __float2half_rn(e2), h3 = __float2half_rn(e3);
                    __half h4 = __float2half_rn(e4), h5 = __float2half_rn(e5);
                    __half h6 = __float2half_rn(e6), h7 = __float2half_rn(e7);
                    ph[0] = pack_h2(h0, h1);
                    ph[1] = pack_h2(h2, h3);
                    ph[2] = pack_h2(h4, h5);
                    ph[3] = pack_h2(h6, h7);
                    pl[0] = pack_h2(__float2half_rn(e0 - __half2float(h0)),
                                    __float2half_rn(e1 - __half2float(h1)));
                    pl[1] = pack_h2(__float2half_rn(e2 - __half2float(h2)),
                                    __float2half_rn(e3 - __half2float(h3)));
                    pl[2] = pack_h2(__float2half_rn(e4 - __half2float(h4)),
                                    __float2half_rn(e5 - __half2float(h5)));
                    pl[3] = pack_h2(__float2half_rn(e6 - __half2float(h6)),
                                    __float2half_rn(e7 - __half2float(h7)));
                }
                int j0 = kk * 16;
                uint32_t v0[4], v16[4];
                uint32_t roff = (uint32_t)(j0 + vrow) * 80;
                ldm_x4_t(v0[0], v0[1], v0[2], v0[3],  vhB + roff + (uint32_t)vcol * 2);
                ldm_x4_t(v16[0], v16[1], v16[2], v16[3],
                         vhB + roff + (uint32_t)(16 + vcol) * 2);
                mma_f16(o[0], ph, v0[0], v0[1]);
                mma_f16(o[1], ph, v0[2], v0[3]);
                mma_f16(o[2], ph, v16[0], v16[1]);
                mma_f16(o[3], ph, v16[2], v16[3]);
                mma_f16(o[0], pl, v0[0], v0[1]);
                mma_f16(o[1], pl, v0[2], v0[3]);
                mma_f16(o[2], pl, v16[0], v16[1]);
                mma_f16(o[3], pl, v16[2], v16[3]);
            }
        }

        // ---- store ----------------------------------------------------------
        {
            int rowA = r0 + g;
            int rowB = rowA + 8;
            if (rowA < NTOK) {
                float* dst = out + ((size_t)b * NTOK + rowA) * DIMC + h * HD;
#pragma unroll
                for (int n = 0; n < 4; n++) {
                    float2 v = {o[n][0], o[n][1]};
                    *(float2*)(dst + n * 8 + 2 * t) = v;
                }
            }
            if (rowB < NTOK) {
                float* dst = out + ((size_t)b * NTOK + rowB) * DIMC + h * HD;
#pragma unroll
                for (int n = 0; n < 4; n++) {
                    float2 v = {o[n][2], o[n][3]};
                    *(float2*)(dst + n * 8 + 2 * t) = v;
                }
            }
        }
    }
}

// ------------------------- launch ------------------------------------------

extern "C" void kernel_launch(void* const* d_in, const int* in_sizes, int n_in,
                              void* d_out, int out_size)
{
    const float* x         = (const float*)d_in[0];
    const float* mask      = (const float*)d_in[1];
    const float* qkv_w     = (const float*)d_in[2];
    const float* qkv_b     = (const float*)d_in[3];
    const float* rel_table = (const float*)d_in[4];
    const int*   rel_index = (const int*)  d_in[5];
    float* out = (float*)d_out;

    prep_a<<<(GM * GK + 255) / 256, 256>>>(x);
    prep_b<<<(GN * GK + 255) / 256, 256>>>(qkv_w);
    prep_bias<<<(NHEAD * NTOK * NTOK + 255) / 256, 256>>>(rel_table, rel_index);

    cudaFuncSetAttribute(qkv_mma, cudaFuncAttributeMaxDynamicSharedMemorySize,
                         SMEM_TOTAL);
    dim3 g1(GN / 128, GM / 128);    // (18, 196)
    qkv_mma<<<g1, 256, SMEM_TOTAL>>>(qkv_b);

    dim3 g2(NHEAD, B_);             // (24, 256)
    attn_tc<<<g2, 128>>>(mask, out);
}